// round 15
// baseline (speedup 1.0000x reference)
#include <cuda_runtime.h>
#include <math_constants.h>
#include <math.h>

#define E 4
#define L 8
#define S 512
#define F 32
#define SAMPLE 512
#define ELF (E * L * F)      /* 1024 */
#define NB1 1024             /* k_proj blocks: 32 el x 32 subtiles of 16 rows */

typedef unsigned long long ull;

// ---------------- scratch (no allocations allowed) ----------------
__device__ float g_projT[ELF * S];            // [e][l][g][s]  raw proj (pre-std-scale)
__device__ float g_red[ELF * SAMPLE];         // red = ksum/len per (row, grid point)
__device__ float g_sp1[NB1 * 32];             // per-subtile per-f partial sum
__device__ float g_sp2[NB1 * 32];             // per-subtile per-f partial sumsq
__device__ float g_bmin[NB1], g_bmax[NB1];
__device__ float g_c[4];                      // 0:uscale 1:qleft 2:h 3:scale_out
__device__ float g_store[6 * L * F];          // per-pair summed |diff|
__device__ unsigned g_cnt1 = 0;               // last-block counters (self-resetting)
__device__ unsigned g_cnt3 = 0;

__device__ __forceinline__ float ex2(float x) {
    float y; asm("ex2.approx.ftz.f32 %0, %1;" : "=f"(y) : "f"(x)); return y;
}
// f32x2 packed helpers (Blackwell packed fp32 pipe)
__device__ __forceinline__ ull pk2(float a, float b) {
    ull r; asm("mov.b64 %0, {%1, %2};" : "=l"(r) : "f"(a), "f"(b)); return r;
}
__device__ __forceinline__ void upk2(ull v, float& a, float& b) {
    asm("mov.b64 {%0, %1}, %2;" : "=f"(a), "=f"(b) : "l"(v));
}
__device__ __forceinline__ ull mul2(ull a, ull b) {
    ull r; asm("mul.rn.f32x2 %0, %1, %2;" : "=l"(r) : "l"(a), "l"(b)); return r;
}
__device__ __forceinline__ ull add2(ull a, ull b) {
    ull r; asm("add.rn.f32x2 %0, %1, %2;" : "=l"(r) : "l"(a), "l"(b)); return r;
}
__device__ __forceinline__ ull fma2(ull a, ull b, ull c) {
    ull r; asm("fma.rn.f32x2 %0, %1, %2, %3;" : "=l"(r) : "l"(a), "l"(b), "l"(c)); return r;
}

// ---------------- K1: proj (16-row tiles, 1024 blocks) + stats; last block -> scalars ----------------
__global__ void __launch_bounds__(128) k_proj(const float* __restrict__ matrix,
                                              const float* __restrict__ params) {
    __shared__ float sp[F * F];          // 4 KB
    __shared__ float mt[16 * F];         // 2 KB
    __shared__ float tr[F * 17];         // transpose staging, pad 17 (no conflicts)
    __shared__ float rs[128], rmn[128], rmx[128], rsq[128];
    __shared__ int is_last;
    int b = blockIdx.x;                  // el*32 + ts
    int el = b >> 5;
    int ts = b & 31;
    int tid = threadIdx.x;
    int g = tid & 31, rg = tid >> 5;     // warp id = row-group (4 rows each)

    // loads
    {
        const float4* p4 = (const float4*)params;
        ((float4*)sp)[tid] = p4[tid];
        ((float4*)sp)[tid + 128] = p4[tid + 128];
        const float4* m4 = (const float4*)(matrix + ((size_t)el * S + (size_t)ts * 16) * F);
        ((float4*)mt)[tid] = m4[tid];
    }
    __syncthreads();

    // std partials: thread covers rows rg*4..rg*4+3 at f = g
    {
        float s1 = 0.f, s2 = 0.f;
        #pragma unroll
        for (int k = 0; k < 4; k++) {
            float x = mt[(rg * 4 + k) * F + g];
            s1 += x; s2 += x * x;
        }
        rs[tid] = s1; rsq[tid] = s2;
    }

    // GEMM: 4 independent row chains; rows rg*4+k, column g
    float acc[4] = {0.f, 0.f, 0.f, 0.f};
    #pragma unroll
    for (int f = 0; f < F; f++) {
        float pv = sp[f * F + g];                 // stride-1, conflict-free
        #pragma unroll
        for (int k = 0; k < 4; k++)
            acc[k] += mt[(rg * 4 + k) * F + f] * pv;   // warp-uniform broadcast
    }
    float mn = CUDART_INF_F, mx = -CUDART_INF_F;
    #pragma unroll
    for (int k = 0; k < 4; k++) {
        tr[g * 17 + rg * 4 + k] = acc[k];         // 17-stride: all banks distinct
        mn = fminf(mn, acc[k]); mx = fmaxf(mx, acc[k]);
    }
    rmn[tid] = mn; rmx[tid] = mx;
    __syncthreads();

    // coalesced transposed store: gg = tid>>2 (32 g), j = tid&3 (4 rows each)
    {
        int gg = tid >> 2, j = tid & 3;
        float4 v = make_float4(tr[gg * 17 + j * 4],     tr[gg * 17 + j * 4 + 1],
                               tr[gg * 17 + j * 4 + 2], tr[gg * 17 + j * 4 + 3]);
        *(float4*)(g_projT + ((size_t)el * F + gg) * S + (size_t)ts * 16 + j * 4) = v;
    }

    for (int st = 64; st; st >>= 1) {
        if (tid < st) {
            rmn[tid] = fminf(rmn[tid], rmn[tid + st]);
            rmx[tid] = fmaxf(rmx[tid], rmx[tid + st]);
            if (st >= 32) { rs[tid] += rs[tid + st]; rsq[tid] += rsq[tid + st]; }
        }
        __syncthreads();
    }
    if (tid < 32) { g_sp1[b * 32 + tid] = rs[tid]; g_sp2[b * 32 + tid] = rsq[tid]; }
    if (tid == 0) { g_bmin[b] = rmn[0]; g_bmax[b] = rmx[0]; }

    // ---- last block finalizes scalars ----
    __threadfence();
    if (tid == 0) is_last = (atomicAdd(&g_cnt1, 1u) == (NB1 - 1u));
    __syncthreads();
    if (!is_last) return;
    __threadfence();

    float sdsum = 0.f;
    for (int c = tid; c < ELF; c += 128) {
        int cel = c >> 5, f = c & 31;
        float s1 = 0.f, s2 = 0.f;
        #pragma unroll 8
        for (int st = 0; st < 32; st++) {
            int idx = ((cel * 32 + st) << 5) + f;
            s1 += g_sp1[idx]; s2 += g_sp2[idx];
        }
        float mean = s1 / (float)S;
        float var = (s2 - s1 * mean) / (float)(S - 1);
        sdsum += sqrtf(fmaxf(var, 0.f));
    }
    float mn2 = CUDART_INF_F, mx2 = -CUDART_INF_F;
    for (int i = tid; i < NB1; i += 128) {
        mn2 = fminf(mn2, g_bmin[i]); mx2 = fmaxf(mx2, g_bmax[i]);
    }
    rs[tid] = sdsum; rmn[tid] = mn2; rmx[tid] = mx2;
    __syncthreads();
    for (int st = 64; st; st >>= 1) {
        if (tid < st) {
            rs[tid] += rs[tid + st];
            rmn[tid] = fminf(rmn[tid], rmn[tid + st]);
            rmx[tid] = fmaxf(rmx[tid], rmx[tid + st]);
        }
        __syncthreads();
    }
    if (tid == 0) {
        float stdv = rs[0] / (float)ELF;
        // mean(std(matrix/stdv)) == 1 exactly (positive homogeneity)
        float bw = 1.06f * powf((float)S, -0.2f);
        float left = rmn[0] / stdv, right = rmx[0] / stdv;
        float range = right - left;
        float delta = range / (float)SAMPLE;
        float gstep = range / (float)(SAMPLE - 1);
        float coef = (0.5f / (bw * bw)) * 1.4426950408889634f;  // fold log2(e)
        float sa = sqrtf(coef);
        float divisor = sqrtf(2.f * CUDART_PI_F) * bw;
        g_c[0] = sa / stdv;                 // uscale
        g_c[1] = left * sa;                 // qleft (scaled)
        g_c[2] = gstep * sa;                // qstep h (scaled)
        g_c[3] = delta / (2.f * divisor);   // final per-pair scale
        g_cnt1 = 0;                         // self-reset for next graph replay
    }
}

// ---------------- K2: hot KDE — factored geometric recurrence (EXACT) ----------------
// K(u,p) = 2^{-(t0 - dp h)^2} = c * g^dp * W_dp; W_dp sample-independent.
// Masked-tail identity: (ksum - corr)/len == sum_{s<len} K/len -> only sum s<len.
// 8 warps per row; each sums 1/8 of the samples; partials combined via smem (fixed order).
__global__ void __launch_bounds__(256, 6) k_kde(const int* __restrict__ data_len) {
    __shared__ float su[S];
    __shared__ float part[8][SAMPLE];
    int elf = blockIdx.x;                // one (e,l,f) row per block
    int el = elf >> 5;
    int tid = threadIdx.x;
    int warp = tid >> 5, lane = tid & 31;
    int len = data_len[el];
    float uscale = g_c[0], qleft = g_c[1], h = g_c[2];
    const float* src = g_projT + (size_t)elf * S;
    for (int s = tid; s < len; s += 256) su[s] = src[s] * uscale;
    __syncthreads();

    int eighth = (len + 7) >> 3;
    int sBeg = warp * eighth;
    int sEnd = min(sBeg + eighth, len);

    float twoh = 2.0f * h;
    float qb = qleft + (float)(lane << 4) * h;   // chunk base: 16 contiguous points per lane
    float m2hqb = -twoh * qb;
    ull a0, a1, a2, a3, a4, a5, a6, a7;
    a0 = a1 = a2 = a3 = a4 = a5 = a6 = a7 = pk2(0.f, 0.f);

    #pragma unroll 2
    for (int s = sBeg; s < sEnd; s++) {
        float u = su[s];
        float t0 = u - qb;
        float c = ex2(__fmul_rn(t0, -t0));
        float gv = ex2(fmaf(u, twoh, m2hqb));
        float g2 = gv * gv;
        float g4 = g2 * g2;
        float g8 = g4 * g4;
        ull gg = pk2(g2, g2);
        ull G8 = pk2(g8, g8);
        ull tA = pk2(c, c * gv);                 // points (0,1)
        a4 = fma2(tA, G8, a4); a0 = add2(a0, tA); tA = mul2(tA, gg);
        a5 = fma2(tA, G8, a5); a1 = add2(a1, tA); tA = mul2(tA, gg);
        a6 = fma2(tA, G8, a6); a2 = add2(a2, tA); tA = mul2(tA, gg);
        a7 = fma2(tA, G8, a7); a3 = add2(a3, tA);
    }

    float* pw = part[warp] + (lane << 4);
    upk2(a0, pw[0],  pw[1]);   upk2(a1, pw[2],  pw[3]);
    upk2(a2, pw[4],  pw[5]);   upk2(a3, pw[6],  pw[7]);
    upk2(a4, pw[8],  pw[9]);   upk2(a5, pw[10], pw[11]);
    upk2(a6, pw[12], pw[13]);  upk2(a7, pw[14], pw[15]);
    __syncthreads();

    // combine 8 warp-partials, apply W_dp and 1/len, write 2 points per thread
    float invlen = 1.0f / (float)len;
    int pt0 = tid << 1;
    float tmp[2];
    #pragma unroll
    for (int i = 0; i < 2; i++) {
        int pt = pt0 + i;
        float ssumv = ((part[0][pt] + part[1][pt]) + (part[2][pt] + part[3][pt]))
                    + ((part[4][pt] + part[5][pt]) + (part[6][pt] + part[7][pt]));
        float dh = (float)(pt & 15) * h;
        tmp[i] = ssumv * ex2(__fmul_rn(dh, -dh)) * invlen;
    }
    *(float2*)(g_red + (size_t)elf * SAMPLE + pt0) = make_float2(tmp[0], tmp[1]);
}

// ---------------- K3: pairwise |diff| sums (shuffle reduce); last block emits output ----------------
// pair order (i<j): 0:(0,1) 1:(0,2) 2:(0,3) 3:(1,2) 4:(1,3) 5:(2,3); train = {0,1,3}
__global__ void __launch_bounds__(256) k_pair(float* __restrict__ out) {
    __shared__ float swarp[6][8];
    __shared__ float sfinal[6];
    __shared__ int is_last;
    int b = blockIdx.x;                 // l*F + f
    int tid = threadIdx.x;
    int warp = tid >> 5, lane = tid & 31;

    float local[6];
    #pragma unroll
    for (int p = 0; p < 6; p++) local[p] = 0.f;
    #pragma unroll
    for (int halfi = 0; halfi < 2; halfi++) {
        int pt = tid + halfi * 256;
        float r[E];
        #pragma unroll
        for (int e = 0; e < E; e++)
            r[e] = g_red[((size_t)(e * 256 + b)) * SAMPLE + pt];
        int p = 0;
        #pragma unroll
        for (int i = 0; i < E; i++)
            #pragma unroll
            for (int j = i + 1; j < E; j++)
                local[p++] += fabsf(r[i] - r[j]);
    }
    #pragma unroll
    for (int p = 0; p < 6; p++) {
        #pragma unroll
        for (int o = 16; o; o >>= 1)
            local[p] += __shfl_down_sync(0xffffffffu, local[p], o);
    }
    if (lane == 0)
        #pragma unroll
        for (int p = 0; p < 6; p++) swarp[p][warp] = local[p];
    __syncthreads();
    if (warp == 0) {
        #pragma unroll
        for (int p = 0; p < 6; p++) {
            float v = (lane < 8) ? swarp[p][lane] : 0.f;
            #pragma unroll
            for (int o = 4; o; o >>= 1)
                v += __shfl_down_sync(0xffffffffu, v, o);
            if (lane == 0) sfinal[p] = v;
        }
        __syncwarp();
        if (lane < 6) g_store[lane * 256 + b] = sfinal[lane];
    }

    // ---- last block: maxima over pairs + scalars -> output ----
    __threadfence();
    if (tid == 0) is_last = (atomicAdd(&g_cnt3, 1u) == 255u);
    __syncthreads();
    if (!is_last) return;
    __threadfence();

    __shared__ float str[256], ste[256];
    float sc = g_c[3];
    float s0 = g_store[0 * 256 + tid], s1 = g_store[1 * 256 + tid], s2 = g_store[2 * 256 + tid];
    float s3 = g_store[3 * 256 + tid], s4 = g_store[4 * 256 + tid], s5 = g_store[5 * 256 + tid];
    float te = fmaxf(fmaxf(fmaxf(s0, s1), fmaxf(s2, s3)), fmaxf(s4, s5)) * sc;
    float tr = fmaxf(fmaxf(s0, s1), s3) * sc;
    out[tid] = tr;          // train_results (L,F)
    out[256 + tid] = te;    // test_results  (L,F)
    str[tid] = tr; ste[tid] = te;
    __syncthreads();
    if (tid < 32) {
        float mtr = -CUDART_INF_F, mte = -CUDART_INF_F;
        #pragma unroll
        for (int l = 0; l < L; l++) {
            mtr = fmaxf(mtr, str[l * 32 + tid]);
            mte = fmaxf(mte, ste[l * 32 + tid]);
        }
        #pragma unroll
        for (int o = 16; o; o >>= 1) {
            mtr += __shfl_down_sync(0xffffffffu, mtr, o);
            mte += __shfl_down_sync(0xffffffffu, mte, o);
        }
        if (tid == 0) {
            out[512] = mtr / 32.f;
            out[513] = mte / 32.f;
            g_cnt3 = 0;          // self-reset for next graph replay
        }
    }
}

extern "C" void kernel_launch(void* const* d_in, const int* in_sizes, int n_in,
                              void* d_out, int out_size) {
    const float* matrix   = (const float*)d_in[0];   // (E,L,S,F) f32
    const float* params   = (const float*)d_in[1];   // (F,F) f32
    const int*   data_len = (const int*)d_in[2];     // (E,L) i32
    float* out = (float*)d_out;                      // 514 f32

    k_proj<<<NB1, 128>>>(matrix, params);
    k_kde<<<ELF, 256>>>(data_len);
    k_pair<<<L * F, 256>>>(out);
}

// round 16
// speedup vs baseline: 1.5250x; 1.5250x over previous
#include <cuda_runtime.h>
#include <math_constants.h>
#include <math.h>

#define E 4
#define L 8
#define S 512
#define F 32
#define SAMPLE 512
#define ELF (E * L * F)      /* 1024 */
#define NB1 256              /* k_proj blocks: 32 el x 8 tiles of 64 rows */

typedef unsigned long long ull;

// ---------------- scratch (no allocations allowed) ----------------
__device__ float g_projT[ELF * S];            // [e][l][g][s]  raw proj (pre-std-scale)
__device__ float g_red[ELF * SAMPLE];         // red = ksum/len per (row, grid point)
__device__ float g_sp1[NB1 * 32];             // per-tile per-f partial sum
__device__ float g_sp2[NB1 * 32];             // per-tile per-f partial sumsq
__device__ float g_bmin[NB1], g_bmax[NB1];
__device__ float g_c[4];                      // 0:uscale 1:qleft 2:h 3:scale_out
__device__ float g_store[6 * L * F];          // per-pair summed |diff|
__device__ unsigned g_cnt1 = 0;               // last-block counters (self-resetting)
__device__ unsigned g_cnt3 = 0;

__device__ __forceinline__ float ex2(float x) {
    float y; asm("ex2.approx.ftz.f32 %0, %1;" : "=f"(y) : "f"(x)); return y;
}
// f32x2 packed helpers (Blackwell packed fp32 pipe)
__device__ __forceinline__ ull pk2(float a, float b) {
    ull r; asm("mov.b64 %0, {%1, %2};" : "=l"(r) : "f"(a), "f"(b)); return r;
}
__device__ __forceinline__ void upk2(ull v, float& a, float& b) {
    asm("mov.b64 {%0, %1}, %2;" : "=f"(a), "=f"(b) : "l"(v));
}
__device__ __forceinline__ ull mul2(ull a, ull b) {
    ull r; asm("mul.rn.f32x2 %0, %1, %2;" : "=l"(r) : "l"(a), "l"(b)); return r;
}
__device__ __forceinline__ ull add2(ull a, ull b) {
    ull r; asm("add.rn.f32x2 %0, %1, %2;" : "=l"(r) : "l"(a), "l"(b)); return r;
}
__device__ __forceinline__ ull fma2(ull a, ull b, ull c) {
    ull r; asm("fma.rn.f32x2 %0, %1, %2, %3;" : "=l"(r) : "l"(a), "l"(b), "l"(c)); return r;
}

// ---------------- K1: proj + std partials + min/max; last block finalizes scalars ----------------
// 256 blocks x 512 threads; tile = 64 s-rows. Transpose staging padded (stride 65): conflict-free.
__global__ void __launch_bounds__(512) k_proj(const float* __restrict__ matrix,
                                              const float* __restrict__ params) {
    __shared__ float sp[F * F];          // 4 KB
    __shared__ float mt[64 * F];         // 8 KB
    __shared__ float tr[F * 65];         // padded transpose staging (8.45 KB)
    __shared__ float rs[512], rsq[512], rmn[512], rmx[512];
    __shared__ int is_last;
    int b = blockIdx.x;                  // el*8 + stile
    int el = b >> 3;
    int stile = b & 7;
    int tid = threadIdx.x;
    int g = tid & 31, rg = tid >> 5;     // rg in 0..15

    // vectorized loads
    {
        if (tid < 256) ((float4*)sp)[tid] = ((const float4*)params)[tid];
        const float4* m4 = (const float4*)(matrix + ((size_t)el * S + (size_t)stile * 64) * F);
        ((float4*)mt)[tid] = m4[tid];    // 512 float4 = 64 rows x 32 f
    }
    __syncthreads();

    // std partials: thread covers rows {rg + 16k} at f = g
    {
        float s1 = 0.f, s2 = 0.f;
        #pragma unroll
        for (int k = 0; k < 4; k++) {
            float x = mt[(rg + 16 * k) * F + g];
            s1 += x; s2 += x * x;
        }
        rs[tid] = s1; rsq[tid] = s2;
    }

    // GEMM: 4 independent row chains (rows rg+16k, output column g)
    float acc[4] = {0.f, 0.f, 0.f, 0.f};
    #pragma unroll
    for (int f = 0; f < F; f++) {
        float pv = sp[f * F + g];                    // stride-1, conflict-free
        #pragma unroll
        for (int k = 0; k < 4; k++)
            acc[k] += mt[(rg + 16 * k) * F + f] * pv;   // warp-uniform broadcast
    }
    float mn = CUDART_INF_F, mx = -CUDART_INF_F;
    #pragma unroll
    for (int k = 0; k < 4; k++) {
        tr[g * 65 + rg + 16 * k] = acc[k];           // stride 65: conflict-free across g
        mn = fminf(mn, acc[k]); mx = fmaxf(mx, acc[k]);
    }
    rmn[tid] = mn; rmx[tid] = mx;
    __syncthreads();

    // coalesced transposed store: gg = tid>>4 (32 cols), j = tid&15 (4 rows each)
    {
        int gg = tid >> 4, j = tid & 15;
        const float* trow = tr + gg * 65 + j * 4;
        float4 v = make_float4(trow[0], trow[1], trow[2], trow[3]);
        *(float4*)(g_projT + ((size_t)el * F + gg) * S + (size_t)stile * 64 + j * 4) = v;
    }

    for (int st = 256; st; st >>= 1) {
        if (tid < st) {
            rmn[tid] = fminf(rmn[tid], rmn[tid + st]);
            rmx[tid] = fmaxf(rmx[tid], rmx[tid + st]);
            if (st >= 32) { rs[tid] += rs[tid + st]; rsq[tid] += rsq[tid + st]; }
        }
        __syncthreads();
    }
    if (tid < 32) { g_sp1[b * 32 + tid] = rs[tid]; g_sp2[b * 32 + tid] = rsq[tid]; }
    if (tid == 0) { g_bmin[b] = rmn[0]; g_bmax[b] = rmx[0]; }

    // ---- last block finalizes scalars (partials stay at 256x32: cheap) ----
    __threadfence();
    if (tid == 0) is_last = (atomicAdd(&g_cnt1, 1u) == (NB1 - 1u));
    __syncthreads();
    if (!is_last) return;
    __threadfence();

    float sdsum = 0.f;
    for (int c = tid; c < ELF; c += 512) {
        int cel = c >> 5, f = c & 31;
        float s1 = 0.f, s2 = 0.f;
        #pragma unroll
        for (int st = 0; st < 8; st++) {
            int idx = ((cel * 8 + st) << 5) + f;
            s1 += g_sp1[idx]; s2 += g_sp2[idx];
        }
        float mean = s1 / (float)S;
        float var = (s2 - s1 * mean) / (float)(S - 1);
        sdsum += sqrtf(fmaxf(var, 0.f));
    }
    float mn2 = (tid < NB1) ? g_bmin[tid] : CUDART_INF_F;
    float mx2 = (tid < NB1) ? g_bmax[tid] : -CUDART_INF_F;
    rs[tid] = sdsum; rmn[tid] = mn2; rmx[tid] = mx2;
    __syncthreads();
    for (int st = 256; st; st >>= 1) {
        if (tid < st) {
            rs[tid] += rs[tid + st];
            rmn[tid] = fminf(rmn[tid], rmn[tid + st]);
            rmx[tid] = fmaxf(rmx[tid], rmx[tid + st]);
        }
        __syncthreads();
    }
    if (tid == 0) {
        float stdv = rs[0] / (float)ELF;
        // mean(std(matrix/stdv)) == 1 exactly (positive homogeneity)
        float bw = 1.06f * powf((float)S, -0.2f);
        float left = rmn[0] / stdv, right = rmx[0] / stdv;
        float range = right - left;
        float delta = range / (float)SAMPLE;
        float gstep = range / (float)(SAMPLE - 1);
        float coef = (0.5f / (bw * bw)) * 1.4426950408889634f;  // fold log2(e)
        float sa = sqrtf(coef);
        float divisor = sqrtf(2.f * CUDART_PI_F) * bw;
        g_c[0] = sa / stdv;                 // uscale
        g_c[1] = left * sa;                 // qleft (scaled)
        g_c[2] = gstep * sa;                // qstep h (scaled)
        g_c[3] = delta / (2.f * divisor);   // final per-pair scale
        g_cnt1 = 0;                         // self-reset for next graph replay
    }
}

// ---------------- K2: hot KDE — factored geometric recurrence (EXACT) ----------------
// K(u,p) = 2^{-(t0 - dp h)^2} = c * g^dp * W_dp; W_dp sample-independent.
// Masked-tail identity: (ksum - corr)/len == sum_{s<len} K/len -> only sum s<len.
// 8 warps per row; each sums 1/8 of the samples; partials combined via smem (fixed order).
__global__ void __launch_bounds__(256, 6) k_kde(const int* __restrict__ data_len) {
    __shared__ float su[S];
    __shared__ float part[8][SAMPLE];
    int elf = blockIdx.x;                // one (e,l,f) row per block
    int el = elf >> 5;
    int tid = threadIdx.x;
    int warp = tid >> 5, lane = tid & 31;
    int len = data_len[el];
    float uscale = g_c[0], qleft = g_c[1], h = g_c[2];
    const float* src = g_projT + (size_t)elf * S;
    for (int s = tid; s < len; s += 256) su[s] = src[s] * uscale;
    __syncthreads();

    int eighth = (len + 7) >> 3;
    int sBeg = warp * eighth;
    int sEnd = min(sBeg + eighth, len);

    float twoh = 2.0f * h;
    float qb = qleft + (float)(lane << 4) * h;   // chunk base: 16 contiguous points per lane
    float m2hqb = -twoh * qb;
    ull a0, a1, a2, a3, a4, a5, a6, a7;
    a0 = a1 = a2 = a3 = a4 = a5 = a6 = a7 = pk2(0.f, 0.f);

    #pragma unroll 2
    for (int s = sBeg; s < sEnd; s++) {
        float u = su[s];
        float t0 = u - qb;
        float c = ex2(__fmul_rn(t0, -t0));
        float gv = ex2(fmaf(u, twoh, m2hqb));
        float g2 = gv * gv;
        float g4 = g2 * g2;
        float g8 = g4 * g4;
        ull gg = pk2(g2, g2);
        ull G8 = pk2(g8, g8);
        ull tA = pk2(c, c * gv);                 // points (0,1)
        a4 = fma2(tA, G8, a4); a0 = add2(a0, tA); tA = mul2(tA, gg);
        a5 = fma2(tA, G8, a5); a1 = add2(a1, tA); tA = mul2(tA, gg);
        a6 = fma2(tA, G8, a6); a2 = add2(a2, tA); tA = mul2(tA, gg);
        a7 = fma2(tA, G8, a7); a3 = add2(a3, tA);
    }

    float* pw = part[warp] + (lane << 4);
    upk2(a0, pw[0],  pw[1]);   upk2(a1, pw[2],  pw[3]);
    upk2(a2, pw[4],  pw[5]);   upk2(a3, pw[6],  pw[7]);
    upk2(a4, pw[8],  pw[9]);   upk2(a5, pw[10], pw[11]);
    upk2(a6, pw[12], pw[13]);  upk2(a7, pw[14], pw[15]);
    __syncthreads();

    // combine 8 warp-partials, apply W_dp and 1/len, write 2 points per thread
    float invlen = 1.0f / (float)len;
    int pt0 = tid << 1;
    float tmp[2];
    #pragma unroll
    for (int i = 0; i < 2; i++) {
        int pt = pt0 + i;
        float ssumv = ((part[0][pt] + part[1][pt]) + (part[2][pt] + part[3][pt]))
                    + ((part[4][pt] + part[5][pt]) + (part[6][pt] + part[7][pt]));
        float dh = (float)(pt & 15) * h;
        tmp[i] = ssumv * ex2(__fmul_rn(dh, -dh)) * invlen;
    }
    *(float2*)(g_red + (size_t)elf * SAMPLE + pt0) = make_float2(tmp[0], tmp[1]);
}

// ---------------- K3: pairwise |diff| sums (shuffle reduce); last block emits output ----------------
// pair order (i<j): 0:(0,1) 1:(0,2) 2:(0,3) 3:(1,2) 4:(1,3) 5:(2,3); train = {0,1,3}
__global__ void __launch_bounds__(256) k_pair(float* __restrict__ out) {
    __shared__ float swarp[6][8];
    __shared__ float sfinal[6];
    __shared__ int is_last;
    int b = blockIdx.x;                 // l*F + f
    int tid = threadIdx.x;
    int warp = tid >> 5, lane = tid & 31;

    float local[6];
    #pragma unroll
    for (int p = 0; p < 6; p++) local[p] = 0.f;
    #pragma unroll
    for (int halfi = 0; halfi < 2; halfi++) {
        int pt = tid + halfi * 256;
        float r[E];
        #pragma unroll
        for (int e = 0; e < E; e++)
            r[e] = g_red[((size_t)(e * 256 + b)) * SAMPLE + pt];
        int p = 0;
        #pragma unroll
        for (int i = 0; i < E; i++)
            #pragma unroll
            for (int j = i + 1; j < E; j++)
                local[p++] += fabsf(r[i] - r[j]);
    }
    #pragma unroll
    for (int p = 0; p < 6; p++) {
        #pragma unroll
        for (int o = 16; o; o >>= 1)
            local[p] += __shfl_down_sync(0xffffffffu, local[p], o);
    }
    if (lane == 0)
        #pragma unroll
        for (int p = 0; p < 6; p++) swarp[p][warp] = local[p];
    __syncthreads();
    if (warp == 0) {
        #pragma unroll
        for (int p = 0; p < 6; p++) {
            float v = (lane < 8) ? swarp[p][lane] : 0.f;
            #pragma unroll
            for (int o = 4; o; o >>= 1)
                v += __shfl_down_sync(0xffffffffu, v, o);
            if (lane == 0) sfinal[p] = v;
        }
        __syncwarp();
        if (lane < 6) g_store[lane * 256 + b] = sfinal[lane];
    }

    // ---- last block: maxima over pairs + scalars -> output ----
    __threadfence();
    if (tid == 0) is_last = (atomicAdd(&g_cnt3, 1u) == 255u);
    __syncthreads();
    if (!is_last) return;
    __threadfence();

    __shared__ float str[256], ste[256];
    float sc = g_c[3];
    float s0 = g_store[0 * 256 + tid], s1 = g_store[1 * 256 + tid], s2 = g_store[2 * 256 + tid];
    float s3 = g_store[3 * 256 + tid], s4 = g_store[4 * 256 + tid], s5 = g_store[5 * 256 + tid];
    float te = fmaxf(fmaxf(fmaxf(s0, s1), fmaxf(s2, s3)), fmaxf(s4, s5)) * sc;
    float tr = fmaxf(fmaxf(s0, s1), s3) * sc;
    out[tid] = tr;          // train_results (L,F)
    out[256 + tid] = te;    // test_results  (L,F)
    str[tid] = tr; ste[tid] = te;
    __syncthreads();
    if (tid < 32) {
        float mtr = -CUDART_INF_F, mte = -CUDART_INF_F;
        #pragma unroll
        for (int l = 0; l < L; l++) {
            mtr = fmaxf(mtr, str[l * 32 + tid]);
            mte = fmaxf(mte, ste[l * 32 + tid]);
        }
        #pragma unroll
        for (int o = 16; o; o >>= 1) {
            mtr += __shfl_down_sync(0xffffffffu, mtr, o);
            mte += __shfl_down_sync(0xffffffffu, mte, o);
        }
        if (tid == 0) {
            out[512] = mtr / 32.f;
            out[513] = mte / 32.f;
            g_cnt3 = 0;          // self-reset for next graph replay
        }
    }
}

extern "C" void kernel_launch(void* const* d_in, const int* in_sizes, int n_in,
                              void* d_out, int out_size) {
    const float* matrix   = (const float*)d_in[0];   // (E,L,S,F) f32
    const float* params   = (const float*)d_in[1];   // (F,F) f32
    const int*   data_len = (const int*)d_in[2];     // (E,L) i32
    float* out = (float*)d_out;                      // 514 f32

    k_proj<<<NB1, 512>>>(matrix, params);
    k_kde<<<ELF, 256>>>(data_len);
    k_pair<<<L * F, 256>>>(out);
}